// round 5
// baseline (speedup 1.0000x reference)
#include <cuda_runtime.h>
#include <cuda_bf16.h>
#include <math.h>
#include <stdint.h>

// Problem constants
#define B_  64
#define T_  32
#define S_  33
#define V_  32000
#define E_  512
#define H_  1024
#define G4  4096
#define M1  (S_*B_)       // 2112

// step config
#define KS   4            // split-K slices (k16-steps per slice = 16)
#define MT   32           // m-tiles of 128 permuted weight rows
#define NTT  256          // 8 warps

// xg GEMM (fp32, proven)
#define BM 64
#define BN 256
#define BK 16
#define NT 512
#define NTILES (G4/BN)
#define ASTR 66
#define BSTR 260

// A-pack: [nt(32)][mi(8)][ks(64)][lane(32)][reg(4)] u32
#define PACK_U32 (MT*8*64*32*4)   // 2,097,152

// ---------------- device scratch ----------------
__device__ float g_x  [M1 * E_];
__device__ float g_xg [M1 * G4];
__device__ float g_c  [B_ * H_];
__device__ uint32_t g_wpA_hi[PACK_U32];
__device__ uint32_t g_wpA_lo[PACK_U32];
__device__ __nv_bfloat16 g_h_hi[B_ * H_];   // [batch][cell]
__device__ __nv_bfloat16 g_h_lo[B_ * H_];
__device__ float g_part2[KS * MT * 128 * 64];
__device__ unsigned g_cnt2[MT];

typedef unsigned long long u64;

__device__ __forceinline__ void ffma2(u64& d, u64 a, u64 b) {
    asm("fma.rn.f32x2 %0, %1, %2, %0;" : "+l"(d) : "l"(a), "l"(b));
}
__device__ __forceinline__ u64 splat2(float x) {
    u64 r; asm("mov.b64 %0, {%1, %1};" : "=l"(r) : "f"(x)); return r;
}
__device__ __forceinline__ float sigf(float x) {
    return 1.0f / (1.0f + __expf(-x));
}
__device__ __forceinline__ float tanhfast(float x) {
    return 2.0f / (1.0f + __expf(-2.0f * x)) - 1.0f;
}

// mma.sync m16n8k16 bf16 -> f32 (baseline PTX, sm_80+; HMMA in SASS)
__device__ __forceinline__ void mma_bf16(float* d, uint32_t a0, uint32_t a1,
                                         uint32_t a2, uint32_t a3,
                                         uint32_t b0, uint32_t b1) {
    asm volatile(
        "mma.sync.aligned.m16n8k16.row.col.f32.bf16.bf16.f32 "
        "{%0,%1,%2,%3}, {%4,%5,%6,%7}, {%8,%9}, {%0,%1,%2,%3};"
        : "+f"(d[0]), "+f"(d[1]), "+f"(d[2]), "+f"(d[3])
        : "r"(a0), "r"(a1), "r"(a2), "r"(a3), "r"(b0), "r"(b1));
}

// ---------------------------------------------------------------------------
// 0a) Pack w_hh into mma A-fragment order, gate-interleaved, bf16 hi/lo.
//     tile row q = mi*16+row16 -> gate = q>>5, cell-in-tile = q&31
// ---------------------------------------------------------------------------
__global__ void prep_wpack(const float* __restrict__ w_hh) {
    int idx = blockIdx.x * 256 + threadIdx.x;
    if (idx >= PACK_U32) return;
    int r   = idx & 3;
    int ln  = (idx >> 2) & 31;
    int ks  = (idx >> 7) & 63;
    int mi  = (idx >> 13) & 7;
    int nt  = idx >> 16;
    int row16 = (ln >> 2) + ((r & 1) << 3);
    int colp  = (ln & 3) * 2 + ((r >> 1) << 3);
    int q = mi * 16 + row16;
    int gate = q >> 5, cl = q & 31;
    const float* src = w_hh + (size_t)(gate * H_ + nt * 32 + cl) * H_ + ks * 16 + colp;
    float v0 = src[0], v1 = src[1];
    __nv_bfloat16 h0 = __float2bfloat16(v0);
    __nv_bfloat16 h1 = __float2bfloat16(v1);
    __nv_bfloat16 l0 = __float2bfloat16(v0 - __bfloat162float(h0));
    __nv_bfloat16 l1 = __float2bfloat16(v1 - __bfloat162float(h1));
    g_wpA_hi[idx] = (uint32_t)__bfloat16_as_ushort(h0)
                  | ((uint32_t)__bfloat16_as_ushort(h1) << 16);
    g_wpA_lo[idx] = (uint32_t)__bfloat16_as_ushort(l0)
                  | ((uint32_t)__bfloat16_as_ushort(l1) << 16);
}

// 0b) Init recurrent state
__global__ void init_hc_kernel(const float* __restrict__ h0,
                               const float* __restrict__ c0) {
    int idx = blockIdx.x * 256 + threadIdx.x;
    if (idx >= B_ * H_) return;
    float v = h0[idx];
    __nv_bfloat16 hi = __float2bfloat16(v);
    g_h_hi[idx] = hi;
    g_h_lo[idx] = __float2bfloat16(v - __bfloat162float(hi));
    g_c[idx] = c0[idx];
}

// ---------------------------------------------------------------------------
// 1) Gather inputs (one-hot @ Linear == column gather)
// ---------------------------------------------------------------------------
__global__ void build_x_kernel(const float* __restrict__ features,
                               const int*   __restrict__ captions,
                               const float* __restrict__ W_embed,
                               const float* __restrict__ b_embed) {
    int idx = blockIdx.x * blockDim.x + threadIdx.x;
    if (idx >= M1 * E_) return;
    int m = idx >> 9;
    int e = idx & 511;
    int t = m >> 6;
    int b = m & 63;
    float v;
    if (t == 0) {
        v = features[b * E_ + e];
    } else {
        int cap = captions[b * T_ + (t - 1)];
        v = W_embed[e * V_ + cap] + b_embed[e];
    }
    g_x[idx] = v;
}

// ---------------------------------------------------------------------------
// 2) Input projection xg = x @ w_ih^T (fp32, proven R3 kernel)
// ---------------------------------------------------------------------------
__global__ __launch_bounds__(NT, 1)
void gemm_xg(const float* __restrict__ A, const float* __restrict__ Bw,
             float* __restrict__ C) {
    __shared__ float As[2][BK][ASTR];
    __shared__ float Bs[2][BK][BSTR];

    const int tid = threadIdx.x;
    const int nt  = blockIdx.x;
    const int m0  = blockIdx.y * BM;
    const int K   = E_;

    const int ar = (tid & 255) >> 2;
    const int aq = tid & 3;
    const int br = tid >> 2;
    const int bq = tid & 3;

    const float* Ap = A + (size_t)(m0 + ar) * K + aq * 4;
    const float* Bp0 = Bw + (size_t)(nt * BN + br) * K + bq * 4;
    const float* Bp1 = Bw + (size_t)(nt * BN + br + 128) * K + bq * 4;

    const int mg = tid >> 6;
    const int ng = tid & 63;

    u64 acc[4][4];
#pragma unroll
    for (int i = 0; i < 4; i++)
#pragma unroll
        for (int j = 0; j < 4; j++) acc[i][j] = 0ull;

    const int nk = K / BK;

    float4 pa, pb0, pb1;
    if (tid < 256) pa = *(const float4*)Ap;
    pb0 = *(const float4*)Bp0;
    pb1 = *(const float4*)Bp1;

    for (int kt = 0; kt < nk; kt++) {
        const int cur = kt & 1;
        if (tid < 256) {
            As[cur][aq * 4 + 0][ar] = pa.x;
            As[cur][aq * 4 + 1][ar] = pa.y;
            As[cur][aq * 4 + 2][ar] = pa.z;
            As[cur][aq * 4 + 3][ar] = pa.w;
        }
        Bs[cur][bq * 4 + 0][br]       = pb0.x;
        Bs[cur][bq * 4 + 1][br]       = pb0.y;
        Bs[cur][bq * 4 + 2][br]       = pb0.z;
        Bs[cur][bq * 4 + 3][br]       = pb0.w;
        Bs[cur][bq * 4 + 0][br + 128] = pb1.x;
        Bs[cur][bq * 4 + 1][br + 128] = pb1.y;
        Bs[cur][bq * 4 + 2][br + 128] = pb1.z;
        Bs[cur][bq * 4 + 3][br + 128] = pb1.w;
        __syncthreads();

        if (kt + 1 < nk) {
            int off = (kt + 1) * BK;
            if (tid < 256) pa = *(const float4*)(Ap + off);
            pb0 = *(const float4*)(Bp0 + off);
            pb1 = *(const float4*)(Bp1 + off);
        }

#pragma unroll
        for (int kk = 0; kk < BK; kk++) {
            u64 a0 = *(const u64*)&As[cur][kk][mg * 8 + 0];
            u64 a1 = *(const u64*)&As[cur][kk][mg * 8 + 2];
            u64 a2 = *(const u64*)&As[cur][kk][mg * 8 + 4];
            u64 a3 = *(const u64*)&As[cur][kk][mg * 8 + 6];
            float4 b4 = *(const float4*)&Bs[cur][kk][ng * 4];
            u64 sb0 = splat2(b4.x), sb1 = splat2(b4.y);
            u64 sb2 = splat2(b4.z), sb3 = splat2(b4.w);
            ffma2(acc[0][0], a0, sb0); ffma2(acc[0][1], a0, sb1);
            ffma2(acc[0][2], a0, sb2); ffma2(acc[0][3], a0, sb3);
            ffma2(acc[1][0], a1, sb0); ffma2(acc[1][1], a1, sb1);
            ffma2(acc[1][2], a1, sb2); ffma2(acc[1][3], a1, sb3);
            ffma2(acc[2][0], a2, sb0); ffma2(acc[2][1], a2, sb1);
            ffma2(acc[2][2], a2, sb2); ffma2(acc[2][3], a2, sb3);
            ffma2(acc[3][0], a3, sb0); ffma2(acc[3][1], a3, sb1);
            ffma2(acc[3][2], a3, sb2); ffma2(acc[3][3], a3, sb3);
        }
    }

#pragma unroll
    for (int i = 0; i < 4; i++) {
        int m = m0 + mg * 8 + 2 * i;
        float* r0 = C + (size_t)m * G4 + nt * BN + ng * 4;
        float* r1 = r0 + G4;
#pragma unroll
        for (int j = 0; j < 4; j++) {
            float2 v = *(float2*)&acc[i][j];
            r0[j] = v.x;
            r1[j] = v.y;
        }
    }
}

// ---------------------------------------------------------------------------
// 3) Recurrent step: D[tile 128, 64] = Wp @ h^T via mma.sync bf16 hi/lo.
//    8 warps: wm = wid&3 (32 m), wn = wid>>2 (32 n). Warp tile 32x32.
//    Split-K over z; fp32 partials; last CTA runs fused LSTM epilogue.
// ---------------------------------------------------------------------------
__global__ __launch_bounds__(NTT, 1)
void step_kernel(int t,
                 const float* __restrict__ b_ih,
                 const float* __restrict__ b_hh,
                 float* __restrict__ out) {
    const int tid  = threadIdx.x;
    const int wid  = tid >> 5;
    const int lane = tid & 31;
    const int nt   = blockIdx.x;
    const int z    = blockIdx.z;
    const int wm   = wid & 3;
    const int wn   = wid >> 2;
    const int g    = lane >> 2;
    const int tig  = lane & 3;

    float acc[2][4][4];
#pragma unroll
    for (int i = 0; i < 2; i++)
#pragma unroll
        for (int j = 0; j < 4; j++)
#pragma unroll
            for (int c = 0; c < 4; c++) acc[i][j][c] = 0.0f;

    // A fragment base: [nt][mi][ks][lane][4]
    const size_t aBase = ((((size_t)nt * 8 + wm * 2) * 64 + z * 16) * 32 + lane) * 4;
    const uint32_t* aH = g_wpA_hi + aBase;
    const uint32_t* aL = g_wpA_lo + aBase;
    const int TILE_STRIDE = 64 * 32 * 4;   // mi -> mi+1
    const int KSTEP_STRIDE = 32 * 4;       // ks -> ks+1

    // B: h[n][k]; per tile j, reg p: (n = wn*32 + j*8 + g, k = z*256 + ks*16 + tig*2 + p*8)
    const int kOff = z * 256 + tig * 2;
    const __nv_bfloat16* bhp[4];
    const __nv_bfloat16* blp[4];
#pragma unroll
    for (int j = 0; j < 4; j++) {
        int n = wn * 32 + j * 8 + g;
        bhp[j] = g_h_hi + (size_t)n * H_ + kOff;
        blp[j] = g_h_lo + (size_t)n * H_ + kOff;
    }

#pragma unroll 4
    for (int ks = 0; ks < 16; ks++) {
        uint4 a0h = *(const uint4*)(aH + ks * KSTEP_STRIDE);
        uint4 a1h = *(const uint4*)(aH + TILE_STRIDE + ks * KSTEP_STRIDE);
        uint4 a0l = *(const uint4*)(aL + ks * KSTEP_STRIDE);
        uint4 a1l = *(const uint4*)(aL + TILE_STRIDE + ks * KSTEP_STRIDE);

        uint32_t bh[4][2], bl[4][2];
#pragma unroll
        for (int j = 0; j < 4; j++) {
            bh[j][0] = *(const uint32_t*)(bhp[j] + ks * 16);
            bh[j][1] = *(const uint32_t*)(bhp[j] + ks * 16 + 8);
            bl[j][0] = *(const uint32_t*)(blp[j] + ks * 16);
            bl[j][1] = *(const uint32_t*)(blp[j] + ks * 16 + 8);
        }

#pragma unroll
        for (int j = 0; j < 4; j++) {
            // hi*hi
            mma_bf16(acc[0][j], a0h.x, a0h.y, a0h.z, a0h.w, bh[j][0], bh[j][1]);
            mma_bf16(acc[1][j], a1h.x, a1h.y, a1h.z, a1h.w, bh[j][0], bh[j][1]);
            // hi*lo
            mma_bf16(acc[0][j], a0h.x, a0h.y, a0h.z, a0h.w, bl[j][0], bl[j][1]);
            mma_bf16(acc[1][j], a1h.x, a1h.y, a1h.z, a1h.w, bl[j][0], bl[j][1]);
            // lo*hi
            mma_bf16(acc[0][j], a0l.x, a0l.y, a0l.z, a0l.w, bh[j][0], bh[j][1]);
            mma_bf16(acc[1][j], a1l.x, a1l.y, a1l.z, a1l.w, bh[j][0], bh[j][1]);
        }
    }

    // store fp32 partials: row_local = wm*32 + mi*16 + g(+8), col = wn*32 + j*8 + tig*2
    {
        float* base = g_part2 + (size_t)(z * MT + nt) * (128 * 64);
#pragma unroll
        for (int mi = 0; mi < 2; mi++) {
            int r0 = wm * 32 + mi * 16 + g;
#pragma unroll
            for (int j = 0; j < 4; j++) {
                int col = wn * 32 + j * 8 + tig * 2;
                *(float2*)&base[(size_t)r0 * 64 + col] =
                    make_float2(acc[mi][j][0], acc[mi][j][1]);
                *(float2*)&base[(size_t)(r0 + 8) * 64 + col] =
                    make_float2(acc[mi][j][2], acc[mi][j][3]);
            }
        }
    }

    // split-K gate
    __threadfence();
    __shared__ unsigned s_last;
    __syncthreads();
    if (tid == 0) {
        unsigned old = atomicAdd(&g_cnt2[nt], 1u);
        s_last = (old == KS - 1) ? 1u : 0u;
    }
    __syncthreads();
    if (!s_last) return;
    if (tid == 0) g_cnt2[nt] = 0;
    __threadfence();

    // fused LSTM epilogue: 32 cells x 64 batch for this tile
    const int cl = tid >> 3;
    const int bb = (tid & 7) * 8;
    const int cell = nt * 32 + cl;
    float bias[4];
#pragma unroll
    for (int gg = 0; gg < 4; gg++)
        bias[gg] = b_ih[gg * H_ + cell] + b_hh[gg * H_ + cell];

#pragma unroll
    for (int bi = 0; bi < 8; bi++) {
        int b = bb + bi;
        float gv[4];
#pragma unroll
        for (int gg = 0; gg < 4; gg++) {
            float s = g_xg[(size_t)(t * B_ + b) * G4 + gg * H_ + cell] + bias[gg];
#pragma unroll
            for (int zz = 0; zz < KS; zz++)
                s += g_part2[(size_t)(zz * MT + nt) * (128 * 64)
                             + (size_t)(gg * 32 + cl) * 64 + b];
            gv[gg] = s;
        }
        float c = sigf(gv[1]) * g_c[b * H_ + cell] + sigf(gv[0]) * tanhfast(gv[2]);
        float h = sigf(gv[3]) * tanhfast(c);
        g_c[b * H_ + cell] = c;
        out[((size_t)b * S_ + t) * H_ + cell] = h;
        __nv_bfloat16 hh = __float2bfloat16(h);
        g_h_hi[b * H_ + cell] = hh;
        g_h_lo[b * H_ + cell] = __float2bfloat16(h - __bfloat162float(hh));
    }
}

// ---------------------------------------------------------------------------
// Launcher
// ---------------------------------------------------------------------------
extern "C" void kernel_launch(void* const* d_in, const int* in_sizes, int n_in,
                              void* d_out, int out_size) {
    const float* features = (const float*)d_in[0];
    const int*   captions = (const int*)  d_in[1];
    const float* W_embed  = (const float*)d_in[2];
    const float* b_embed  = (const float*)d_in[3];
    const float* w_ih     = (const float*)d_in[4];
    const float* w_hh     = (const float*)d_in[5];
    const float* b_ih     = (const float*)d_in[6];
    const float* b_hh     = (const float*)d_in[7];
    const float* h0       = (const float*)d_in[8];
    const float* c0       = (const float*)d_in[9];
    float* out = (float*)d_out;

    float *px, *pxg;
    cudaGetSymbolAddress((void**)&px,  g_x);
    cudaGetSymbolAddress((void**)&pxg, g_xg);

    // prep: weight fragment-pack + state init + input gather
    prep_wpack<<<(PACK_U32 + 255) / 256, 256>>>(w_hh);
    init_hc_kernel<<<(B_ * H_ + 255) / 256, 256>>>(h0, c0);
    build_x_kernel<<<(M1 * E_ + 255) / 256, 256>>>(features, captions, W_embed, b_embed);

    // input projection
    gemm_xg<<<dim3(NTILES, M1 / BM, 1), NT>>>(px, w_ih, pxg);

    // recurrence: 33 fused HMMA steps
    for (int t = 0; t < S_; t++) {
        step_kernel<<<dim3(MT, 1, KS), NTT>>>(t, b_ih, b_hh, out);
    }
}

// round 6
// speedup vs baseline: 1.1771x; 1.1771x over previous
#include <cuda_runtime.h>
#include <cuda_bf16.h>
#include <math.h>
#include <stdint.h>

// Problem constants
#define B_  64
#define T_  32
#define S_  33
#define V_  32000
#define E_  512
#define H_  1024
#define G4  4096
#define M1  (S_*B_)       // 2112

// recurrence config
#define KS    4           // split-K slices
#define MT    32          // m-tiles of 128 permuted weight rows
#define NTT   256         // 8 warps
#define NCTA  (MT*KS)     // 128 persistent CTAs

// packs
#define PACK_U32  (MT*8*64*32*4)      // w_hh A-frags: 2,097,152 u32
#define XTILES    (M1/16)             // 132 m16-tiles of x
#define XA_U32    (XTILES*32*32*4)    // x A-frags: 540,672 u32
#define WIH_U32   (512*32*32*2)       // w_ih B-frags: 1,048,576 u32

// ---------------- device scratch ----------------
__device__ float g_xg [M1 * G4];
__device__ float g_c  [B_ * H_];
__device__ uint32_t g_wpA_hi[PACK_U32];
__device__ uint32_t g_wpA_lo[PACK_U32];
__device__ uint32_t g_xA_hi[XA_U32];
__device__ uint32_t g_xA_lo[XA_U32];
__device__ uint32_t g_wihB_hi[WIH_U32];
__device__ uint32_t g_wihB_lo[WIH_U32];
__device__ __nv_bfloat16 g_h_hi[B_ * H_];   // [batch][cell]
__device__ __nv_bfloat16 g_h_lo[B_ * H_];
__device__ float g_part2[KS * MT * 128 * 64];
__device__ unsigned g_cnt2[MT];
__device__ unsigned g_bar;                   // persistent grid barrier

__device__ __forceinline__ float sigf(float x) {
    return 1.0f / (1.0f + __expf(-x));
}
__device__ __forceinline__ float tanhfast(float x) {
    return 2.0f / (1.0f + __expf(-2.0f * x)) - 1.0f;
}

// mma.sync m16n8k16 bf16 -> f32 (baseline PTX; HMMA in SASS)
__device__ __forceinline__ void mma_bf16(float* d, uint32_t a0, uint32_t a1,
                                         uint32_t a2, uint32_t a3,
                                         uint32_t b0, uint32_t b1) {
    asm volatile(
        "mma.sync.aligned.m16n8k16.row.col.f32.bf16.bf16.f32 "
        "{%0,%1,%2,%3}, {%4,%5,%6,%7}, {%8,%9}, {%0,%1,%2,%3};"
        : "+f"(d[0]), "+f"(d[1]), "+f"(d[2]), "+f"(d[3])
        : "r"(a0), "r"(a1), "r"(a2), "r"(a3), "r"(b0), "r"(b1));
}
__device__ __forceinline__ uint32_t pack_hi(float v0, float v1,
                                            float& l0, float& l1) {
    __nv_bfloat16 h0 = __float2bfloat16(v0);
    __nv_bfloat16 h1 = __float2bfloat16(v1);
    l0 = v0 - __bfloat162float(h0);
    l1 = v1 - __bfloat162float(h1);
    return (uint32_t)__bfloat16_as_ushort(h0)
         | ((uint32_t)__bfloat16_as_ushort(h1) << 16);
}
__device__ __forceinline__ uint32_t pack_bf2(float v0, float v1) {
    return (uint32_t)__bfloat16_as_ushort(__float2bfloat16(v0))
         | ((uint32_t)__bfloat16_as_ushort(__float2bfloat16(v1)) << 16);
}

// ---------------------------------------------------------------------------
// 0a) Pack w_hh into A-fragment order, gate-interleaved, bf16 hi/lo (proven)
// ---------------------------------------------------------------------------
__global__ void prep_wpack(const float* __restrict__ w_hh) {
    int idx = blockIdx.x * 256 + threadIdx.x;
    if (idx >= PACK_U32) return;
    int r   = idx & 3;
    int ln  = (idx >> 2) & 31;
    int ks  = (idx >> 7) & 63;
    int mi  = (idx >> 13) & 7;
    int nt  = idx >> 16;
    int row16 = (ln >> 2) + ((r & 1) << 3);
    int colp  = (ln & 3) * 2 + ((r >> 1) << 3);
    int q = mi * 16 + row16;
    int gate = q >> 5, cl = q & 31;
    const float* src = w_hh + (size_t)(gate * H_ + nt * 32 + cl) * H_ + ks * 16 + colp;
    float v0 = src[0], v1 = src[1], l0, l1;
    g_wpA_hi[idx] = pack_hi(v0, v1, l0, l1);
    g_wpA_lo[idx] = pack_bf2(l0, l1);
}

// 0b) Pack w_ih into B-fragment order (n8k16 col), bf16 hi/lo
__global__ void prep_wih(const float* __restrict__ w_ih) {
    int idx = blockIdx.x * 256 + threadIdx.x;
    if (idx >= WIH_U32) return;
    int r    = idx & 1;
    int lane = (idx >> 1) & 31;
    int ks   = (idx >> 6) & 31;
    int n8   = idx >> 11;
    int n = n8 * 8 + (lane >> 2);
    int k = ks * 16 + (lane & 3) * 2 + r * 8;
    const float* src = w_ih + (size_t)n * E_ + k;
    float v0 = src[0], v1 = src[1], l0, l1;
    g_wihB_hi[idx] = pack_hi(v0, v1, l0, l1);
    g_wihB_lo[idx] = pack_bf2(l0, l1);
}

// 0c) Build x directly in A-fragment order (gather fused with pack)
__global__ void build_x_pack(const float* __restrict__ features,
                             const int*   __restrict__ captions,
                             const float* __restrict__ W_embed,
                             const float* __restrict__ b_embed) {
    int idx = blockIdx.x * 256 + threadIdx.x;
    if (idx >= XA_U32) return;
    int rr   = idx & 3;
    int lane = (idx >> 2) & 31;
    int ks   = (idx >> 7) & 31;
    int mt   = idx >> 12;
    int row16 = (lane >> 2) + ((rr & 1) << 3);
    int colp  = (lane & 3) * 2 + ((rr >> 1) << 3);
    int m = mt * 16 + row16;
    int k = ks * 16 + colp;
    int t = m >> 6, b = m & 63;
    float v0, v1;
    if (t == 0) {
        v0 = features[b * E_ + k];
        v1 = features[b * E_ + k + 1];
    } else {
        int cap = captions[b * T_ + (t - 1)];
        v0 = W_embed[(size_t)k * V_ + cap] + b_embed[k];
        v1 = W_embed[(size_t)(k + 1) * V_ + cap] + b_embed[k + 1];
    }
    float l0, l1;
    g_xA_hi[idx] = pack_hi(v0, v1, l0, l1);
    g_xA_lo[idx] = pack_bf2(l0, l1);
}

// 0d) Init recurrent state
__global__ void init_hc_kernel(const float* __restrict__ h0,
                               const float* __restrict__ c0) {
    int idx = blockIdx.x * 256 + threadIdx.x;
    if (idx >= B_ * H_) return;
    float v = h0[idx];
    __nv_bfloat16 hi = __float2bfloat16(v);
    g_h_hi[idx] = hi;
    g_h_lo[idx] = __float2bfloat16(v - __bfloat162float(hi));
    g_c[idx] = c0[idx];
}

// ---------------------------------------------------------------------------
// 1) xg = x @ w_ih^T + (b_ih + b_hh), bf16 hi/lo 3-term HMMA, fragment LDGs.
//    grid (33, 32): 64m x 128n per CTA; 8 warps = 2m x 4n, warp 32m x 32n.
// ---------------------------------------------------------------------------
__global__ __launch_bounds__(NTT, 1)
void gemm_xg_bf16(const float* __restrict__ b_ih,
                  const float* __restrict__ b_hh,
                  float* __restrict__ C) {
    const int tid  = threadIdx.x;
    const int wid  = tid >> 5;
    const int lane = tid & 31;
    const int wm   = wid & 1;
    const int wn   = wid >> 1;
    const int mt0  = blockIdx.x * 4 + wm * 2;
    const int n8_0 = blockIdx.y * 16 + wn * 4;
    const int g    = lane >> 2;
    const int tig  = lane & 3;

    const uint4* aH = (const uint4*)g_xA_hi;
    const uint4* aL = (const uint4*)g_xA_lo;
    const uint2* bH = (const uint2*)g_wihB_hi;
    const uint2* bL = (const uint2*)g_wihB_lo;

    float acc[2][4][4];
#pragma unroll
    for (int i = 0; i < 2; i++)
#pragma unroll
        for (int j = 0; j < 4; j++)
#pragma unroll
            for (int c = 0; c < 4; c++) acc[i][j][c] = 0.0f;

#pragma unroll 4
    for (int ks = 0; ks < 32; ks++) {
        uint4 ah[2], al[2];
#pragma unroll
        for (int mi = 0; mi < 2; mi++) {
            size_t ai = ((size_t)(mt0 + mi) * 32 + ks) * 32 + lane;
            ah[mi] = __ldg(&aH[ai]);
            al[mi] = __ldg(&aL[ai]);
        }
        uint2 bh[4], bl[4];
#pragma unroll
        for (int j = 0; j < 4; j++) {
            size_t bix = ((size_t)(n8_0 + j) * 32 + ks) * 32 + lane;
            bh[j] = __ldg(&bH[bix]);
            bl[j] = __ldg(&bL[bix]);
        }
#pragma unroll
        for (int j = 0; j < 4; j++) {
#pragma unroll
            for (int mi = 0; mi < 2; mi++) {
                mma_bf16(acc[mi][j], ah[mi].x, ah[mi].y, ah[mi].z, ah[mi].w,
                         bh[j].x, bh[j].y);
                mma_bf16(acc[mi][j], ah[mi].x, ah[mi].y, ah[mi].z, ah[mi].w,
                         bl[j].x, bl[j].y);
                mma_bf16(acc[mi][j], al[mi].x, al[mi].y, al[mi].z, al[mi].w,
                         bh[j].x, bh[j].y);
            }
        }
    }

    // epilogue: add (b_ih+b_hh)[n], store fp32
#pragma unroll
    for (int j = 0; j < 4; j++) {
        int n = (n8_0 + j) * 8 + tig * 2;
        float bx = b_ih[n] + b_hh[n];
        float by = b_ih[n + 1] + b_hh[n + 1];
#pragma unroll
        for (int mi = 0; mi < 2; mi++) {
            int m0r = (mt0 + mi) * 16 + g;
            *(float2*)&C[(size_t)m0r * G4 + n] =
                make_float2(acc[mi][j][0] + bx, acc[mi][j][1] + by);
            *(float2*)&C[(size_t)(m0r + 8) * G4 + n] =
                make_float2(acc[mi][j][2] + bx, acc[mi][j][3] + by);
        }
    }
}

// ---------------------------------------------------------------------------
// 2) Persistent recurrence: 128 CTAs run all 33 steps with a grid barrier.
//    Per step: bf16 hi/lo HMMA split-K GEMM -> partials -> winner CTA does
//    fused LSTM epilogue -> grid barrier. Cross-CTA data read via __ldcg.
// ---------------------------------------------------------------------------
__global__ __launch_bounds__(NTT, 1)
void rnn_persistent(float* __restrict__ out) {
    const int tid  = threadIdx.x;
    const int wid  = tid >> 5;
    const int lane = tid & 31;
    const int nt   = blockIdx.x;
    const int z    = blockIdx.z;
    const int wm   = wid & 3;
    const int wn   = wid >> 2;
    const int g    = lane >> 2;
    const int tig  = lane & 3;

    // A fragment base: [nt][mi][ks(64)][lane][4] u32
    const size_t aBase = ((((size_t)nt * 8 + wm * 2) * 64 + z * 16) * 32 + lane) * 4;
    const uint32_t* aHp = g_wpA_hi + aBase;
    const uint32_t* aLp = g_wpA_lo + aBase;
    const int TILE_STRIDE  = 64 * 32 * 4;
    const int KSTEP_STRIDE = 32 * 4;

    const int kOff = z * 256 + tig * 2;
    const uint32_t* bhp[4];
    const uint32_t* blp[4];
#pragma unroll
    for (int j = 0; j < 4; j++) {
        int n = wn * 32 + j * 8 + g;
        bhp[j] = (const uint32_t*)(g_h_hi + (size_t)n * H_ + kOff);
        blp[j] = (const uint32_t*)(g_h_lo + (size_t)n * H_ + kOff);
    }

    const int cl = tid >> 3;
    const int bb = (tid & 7) * 8;
    const int cell = nt * 32 + cl;

    __shared__ unsigned s_last;

    for (int t = 0; t < S_; t++) {
        float acc[2][4][4];
#pragma unroll
        for (int i = 0; i < 2; i++)
#pragma unroll
            for (int j = 0; j < 4; j++)
#pragma unroll
                for (int c = 0; c < 4; c++) acc[i][j][c] = 0.0f;

#pragma unroll 4
        for (int ks = 0; ks < 16; ks++) {
            uint4 a0h = *(const uint4*)(aHp + ks * KSTEP_STRIDE);
            uint4 a1h = *(const uint4*)(aHp + TILE_STRIDE + ks * KSTEP_STRIDE);
            uint4 a0l = *(const uint4*)(aLp + ks * KSTEP_STRIDE);
            uint4 a1l = *(const uint4*)(aLp + TILE_STRIDE + ks * KSTEP_STRIDE);

            uint32_t bh[4][2], bl[4][2];
#pragma unroll
            for (int j = 0; j < 4; j++) {
                bh[j][0] = __ldcg(bhp[j] + ks * 8);      // u32 units: 16 bf16 = 8 u32
                bh[j][1] = __ldcg(bhp[j] + ks * 8 + 4);
                bl[j][0] = __ldcg(blp[j] + ks * 8);
                bl[j][1] = __ldcg(blp[j] + ks * 8 + 4);
            }
#pragma unroll
            for (int j = 0; j < 4; j++) {
                mma_bf16(acc[0][j], a0h.x, a0h.y, a0h.z, a0h.w, bh[j][0], bh[j][1]);
                mma_bf16(acc[1][j], a1h.x, a1h.y, a1h.z, a1h.w, bh[j][0], bh[j][1]);
                mma_bf16(acc[0][j], a0h.x, a0h.y, a0h.z, a0h.w, bl[j][0], bl[j][1]);
                mma_bf16(acc[1][j], a1h.x, a1h.y, a1h.z, a1h.w, bl[j][0], bl[j][1]);
                mma_bf16(acc[0][j], a0l.x, a0l.y, a0l.z, a0l.w, bh[j][0], bh[j][1]);
                mma_bf16(acc[1][j], a1l.x, a1l.y, a1l.z, a1l.w, bh[j][0], bh[j][1]);
            }
        }

        // store fp32 partials
        {
            float* base = g_part2 + (size_t)(z * MT + nt) * (128 * 64);
#pragma unroll
            for (int mi = 0; mi < 2; mi++) {
                int r0 = wm * 32 + mi * 16 + g;
#pragma unroll
                for (int j = 0; j < 4; j++) {
                    int col = wn * 32 + j * 8 + tig * 2;
                    *(float2*)&base[(size_t)r0 * 64 + col] =
                        make_float2(acc[mi][j][0], acc[mi][j][1]);
                    *(float2*)&base[(size_t)(r0 + 8) * 64 + col] =
                        make_float2(acc[mi][j][2], acc[mi][j][3]);
                }
            }
        }

        // per-tile split-K gate
        __threadfence();
        __syncthreads();
        if (tid == 0) {
            unsigned old = atomicAdd(&g_cnt2[nt], 1u);
            s_last = (old == KS - 1) ? 1u : 0u;
        }
        __syncthreads();

        if (s_last) {
            if (tid == 0) g_cnt2[nt] = 0;
            __threadfence();
            // fused LSTM epilogue: 32 cells x 64 batch (bias already in xg)
#pragma unroll
            for (int bi = 0; bi < 8; bi++) {
                int b = bb + bi;
                float gv[4];
#pragma unroll
                for (int gg = 0; gg < 4; gg++) {
                    float s = g_xg[(size_t)(t * B_ + b) * G4 + gg * H_ + cell];
#pragma unroll
                    for (int zz = 0; zz < KS; zz++)
                        s += __ldcg(&g_part2[(size_t)(zz * MT + nt) * (128 * 64)
                                             + (size_t)(gg * 32 + cl) * 64 + b]);
                    gv[gg] = s;
                }
                float cold = __ldcg(&g_c[b * H_ + cell]);
                float c = sigf(gv[1]) * cold + sigf(gv[0]) * tanhfast(gv[2]);
                float h = sigf(gv[3]) * tanhfast(c);
                g_c[b * H_ + cell] = c;
                out[((size_t)b * S_ + t) * H_ + cell] = h;
                __nv_bfloat16 hh = __float2bfloat16(h);
                g_h_hi[b * H_ + cell] = hh;
                g_h_lo[b * H_ + cell] = __float2bfloat16(h - __bfloat162float(hh));
            }
        }

        // grid barrier (monotone counter; last-step arrival resets for replay)
        __syncthreads();
        if (t < S_ - 1) {
            if (tid == 0) {
                __threadfence();
                atomicAdd(&g_bar, 1u);
                unsigned target = (unsigned)NCTA * (t + 1);
                unsigned v;
                do {
                    asm volatile("ld.global.acquire.gpu.u32 %0, [%1];"
                                 : "=r"(v) : "l"(&g_bar));
                } while (v < target);
            }
            __syncthreads();
        } else {
            if (tid == 0) {
                __threadfence();
                unsigned old = atomicAdd(&g_bar, 1u);
                if (old == (unsigned)NCTA * S_ - 1u)
                    atomicExch(&g_bar, 0u);   // reset for next graph replay
            }
        }
    }
}

// ---------------------------------------------------------------------------
// Launcher
// ---------------------------------------------------------------------------
extern "C" void kernel_launch(void* const* d_in, const int* in_sizes, int n_in,
                              void* d_out, int out_size) {
    const float* features = (const float*)d_in[0];
    const int*   captions = (const int*)  d_in[1];
    const float* W_embed  = (const float*)d_in[2];
    const float* b_embed  = (const float*)d_in[3];
    const float* w_ih     = (const float*)d_in[4];
    const float* w_hh     = (const float*)d_in[5];
    const float* b_ih     = (const float*)d_in[6];
    const float* b_hh     = (const float*)d_in[7];
    const float* h0       = (const float*)d_in[8];
    const float* c0       = (const float*)d_in[9];
    float* out = (float*)d_out;

    float* pxg;
    cudaGetSymbolAddress((void**)&pxg, g_xg);

    // prep: weight/input fragment packs + state init
    prep_wpack<<<(PACK_U32 + 255) / 256, 256>>>(w_hh);
    prep_wih<<<(WIH_U32 + 255) / 256, 256>>>(w_ih);
    build_x_pack<<<(XA_U32 + 255) / 256, 256>>>(features, captions, W_embed, b_embed);
    init_hc_kernel<<<(B_ * H_ + 255) / 256, 256>>>(h0, c0);

    // input projection (bias folded in)
    gemm_xg_bf16<<<dim3(M1 / 64, G4 / 128), NTT>>>(b_ih, b_hh, pxg);

    // persistent recurrence: one kernel, 33 steps, internal grid barrier
    rnn_persistent<<<dim3(MT, 1, KS), NTT>>>(out);
}

// round 7
// speedup vs baseline: 1.8601x; 1.5802x over previous
#include <cuda_runtime.h>
#include <cuda_bf16.h>
#include <math.h>
#include <stdint.h>

// Problem constants
#define B_  64
#define T_  32
#define S_  33
#define V_  32000
#define E_  512
#define H_  1024
#define G4  4096
#define M1  (S_*B_)       // 2112

// recurrence config: 128 CTAs x 8 cells, full K, no split-K
#define NCTA  128
#define NTT   256         // 8 warps
#define NKS   64          // k16 steps (K=1024)
#define CHUNK_ROWS 128    // k rows per staged chunk
#define NCHUNK (H_/CHUNK_ROWS)   // 8
#define BSROW  144        // padded smem row bytes (128 data + 16 pad)
#define CHUNK_BYTES (CHUNK_ROWS*BSROW)   // 18432
#define SMEM_SZ (2*2*CHUNK_BYTES)        // 73728 (buf x {hi,lo})

// packs
#define PACK2_U32 (NCTA*2*NKS*32*4)   // w_hh A-frags: 2,097,152 u32
#define XTILES    (M1/16)
#define XA_U32    (XTILES*32*32*4)
#define WIH_U32   (512*32*32*2)

// ---------------- device scratch ----------------
__device__ float g_xg [M1 * G4];
__device__ uint32_t g_wpA2_hi[PACK2_U32];
__device__ uint32_t g_wpA2_lo[PACK2_U32];
__device__ uint32_t g_xA_hi[XA_U32];
__device__ uint32_t g_xA_lo[XA_U32];
__device__ uint32_t g_wihB_hi[WIH_U32];
__device__ uint32_t g_wihB_lo[WIH_U32];
__device__ __nv_bfloat16 g_hT_hi[H_ * B_];   // [cell][batch]
__device__ __nv_bfloat16 g_hT_lo[H_ * B_];
__device__ unsigned g_bar;

__device__ __forceinline__ float sigf(float x) {
    return 1.0f / (1.0f + __expf(-x));
}
__device__ __forceinline__ float tanhfast(float x) {
    return 2.0f / (1.0f + __expf(-2.0f * x)) - 1.0f;
}
__device__ __forceinline__ void mma_bf16(float* d, uint32_t a0, uint32_t a1,
                                         uint32_t a2, uint32_t a3,
                                         uint32_t b0, uint32_t b1) {
    asm volatile(
        "mma.sync.aligned.m16n8k16.row.col.f32.bf16.bf16.f32 "
        "{%0,%1,%2,%3}, {%4,%5,%6,%7}, {%8,%9}, {%0,%1,%2,%3};"
        : "+f"(d[0]), "+f"(d[1]), "+f"(d[2]), "+f"(d[3])
        : "r"(a0), "r"(a1), "r"(a2), "r"(a3), "r"(b0), "r"(b1));
}
__device__ __forceinline__ uint32_t pack_hi(float v0, float v1,
                                            float& l0, float& l1) {
    __nv_bfloat16 h0 = __float2bfloat16(v0);
    __nv_bfloat16 h1 = __float2bfloat16(v1);
    l0 = v0 - __bfloat162float(h0);
    l1 = v1 - __bfloat162float(h1);
    return (uint32_t)__bfloat16_as_ushort(h0)
         | ((uint32_t)__bfloat16_as_ushort(h1) << 16);
}
__device__ __forceinline__ uint32_t pack_bf2(float v0, float v1) {
    return (uint32_t)__bfloat16_as_ushort(__float2bfloat16(v0))
         | ((uint32_t)__bfloat16_as_ushort(__float2bfloat16(v1)) << 16);
}
__device__ __forceinline__ uint32_t smem_u32p(const void* p) {
    uint32_t a;
    asm("{ .reg .u64 t; cvta.to.shared.u64 t, %1; cvt.u32.u64 %0, t; }"
        : "=r"(a) : "l"(p));
    return a;
}
__device__ __forceinline__ void cp16(uint32_t sdst, const void* gsrc) {
    asm volatile("cp.async.cg.shared.global [%0], [%1], 16;"
                 :: "r"(sdst), "l"(gsrc) : "memory");
}
__device__ __forceinline__ void ldsm_x2_t(uint32_t& r0, uint32_t& r1,
                                          uint32_t addr) {
    asm volatile("ldmatrix.sync.aligned.m8n8.x2.trans.shared.b16 {%0,%1}, [%2];"
                 : "=r"(r0), "=r"(r1) : "r"(addr));
}

// ---------------------------------------------------------------------------
// 0a) Pack w_hh into A-frag order: tiles of 32 rows (q = gate*8 + cell)
//     [nt(128)][mi(2)][ks(64)][lane(32)][r(4)]
// ---------------------------------------------------------------------------
__global__ void prep_wpack2(const float* __restrict__ w_hh) {
    int idx = blockIdx.x * 256 + threadIdx.x;
    if (idx >= PACK2_U32) return;
    int r    = idx & 3;
    int lane = (idx >> 2) & 31;
    int ks   = (idx >> 7) & 63;
    int mi   = (idx >> 13) & 1;
    int nt   = idx >> 14;
    int row16 = (lane >> 2) + ((r & 1) << 3);
    int colp  = (lane & 3) * 2 + ((r >> 1) << 3);
    int q = mi * 16 + row16;            // 0..31
    int gate = q >> 3, cl = q & 7;
    const float* src = w_hh + (size_t)(gate * H_ + nt * 8 + cl) * H_ + ks * 16 + colp;
    float v0 = src[0], v1 = src[1], l0, l1;
    g_wpA2_hi[idx] = pack_hi(v0, v1, l0, l1);
    g_wpA2_lo[idx] = pack_bf2(l0, l1);
}

// 0b) Pack w_ih into B-frag order (unchanged, proven)
__global__ void prep_wih(const float* __restrict__ w_ih) {
    int idx = blockIdx.x * 256 + threadIdx.x;
    if (idx >= WIH_U32) return;
    int r    = idx & 1;
    int lane = (idx >> 1) & 31;
    int ks   = (idx >> 6) & 31;
    int n8   = idx >> 11;
    int n = n8 * 8 + (lane >> 2);
    int k = ks * 16 + (lane & 3) * 2 + r * 8;
    const float* src = w_ih + (size_t)n * E_ + k;
    float v0 = src[0], v1 = src[1], l0, l1;
    g_wihB_hi[idx] = pack_hi(v0, v1, l0, l1);
    g_wihB_lo[idx] = pack_bf2(l0, l1);
}

// 0c) Build x in A-frag order (gather fused with pack, proven)
__global__ void build_x_pack(const float* __restrict__ features,
                             const int*   __restrict__ captions,
                             const float* __restrict__ W_embed,
                             const float* __restrict__ b_embed) {
    int idx = blockIdx.x * 256 + threadIdx.x;
    if (idx >= XA_U32) return;
    int rr   = idx & 3;
    int lane = (idx >> 2) & 31;
    int ks   = (idx >> 7) & 31;
    int mt   = idx >> 12;
    int row16 = (lane >> 2) + ((rr & 1) << 3);
    int colp  = (lane & 3) * 2 + ((rr >> 1) << 3);
    int m = mt * 16 + row16;
    int k = ks * 16 + colp;
    int t = m >> 6, b = m & 63;
    float v0, v1;
    if (t == 0) {
        v0 = features[b * E_ + k];
        v1 = features[b * E_ + k + 1];
    } else {
        int cap = captions[b * T_ + (t - 1)];
        v0 = W_embed[(size_t)k * V_ + cap] + b_embed[k];
        v1 = W_embed[(size_t)(k + 1) * V_ + cap] + b_embed[k + 1];
    }
    float l0, l1;
    g_xA_hi[idx] = pack_hi(v0, v1, l0, l1);
    g_xA_lo[idx] = pack_bf2(l0, l1);
}

// 0d) Init h state transposed [cell][batch]
__global__ void init_h_kernel(const float* __restrict__ h0) {
    int idx = blockIdx.x * 256 + threadIdx.x;
    if (idx >= B_ * H_) return;
    int cell = idx >> 6;
    int b    = idx & 63;
    float v = h0[b * H_ + cell];
    __nv_bfloat16 hi = __float2bfloat16(v);
    g_hT_hi[idx] = hi;
    g_hT_lo[idx] = __float2bfloat16(v - __bfloat162float(hi));
}

// ---------------------------------------------------------------------------
// 1) xg = x @ w_ih^T + bias (bf16 hi/lo HMMA, fragment LDGs — proven R6)
// ---------------------------------------------------------------------------
__global__ __launch_bounds__(NTT, 1)
void gemm_xg_bf16(const float* __restrict__ b_ih,
                  const float* __restrict__ b_hh,
                  float* __restrict__ C) {
    const int tid  = threadIdx.x;
    const int wid  = tid >> 5;
    const int lane = tid & 31;
    const int wm   = wid & 1;
    const int wn   = wid >> 1;
    const int mt0  = blockIdx.x * 4 + wm * 2;
    const int n8_0 = blockIdx.y * 16 + wn * 4;
    const int g    = lane >> 2;
    const int tig  = lane & 3;

    const uint4* aH = (const uint4*)g_xA_hi;
    const uint4* aL = (const uint4*)g_xA_lo;
    const uint2* bH = (const uint2*)g_wihB_hi;
    const uint2* bL = (const uint2*)g_wihB_lo;

    float acc[2][4][4];
#pragma unroll
    for (int i = 0; i < 2; i++)
#pragma unroll
        for (int j = 0; j < 4; j++)
#pragma unroll
            for (int c = 0; c < 4; c++) acc[i][j][c] = 0.0f;

#pragma unroll 4
    for (int ks = 0; ks < 32; ks++) {
        uint4 ah[2], al[2];
#pragma unroll
        for (int mi = 0; mi < 2; mi++) {
            size_t ai = ((size_t)(mt0 + mi) * 32 + ks) * 32 + lane;
            ah[mi] = __ldg(&aH[ai]);
            al[mi] = __ldg(&aL[ai]);
        }
        uint2 bh[4], bl[4];
#pragma unroll
        for (int j = 0; j < 4; j++) {
            size_t bix = ((size_t)(n8_0 + j) * 32 + ks) * 32 + lane;
            bh[j] = __ldg(&bH[bix]);
            bl[j] = __ldg(&bL[bix]);
        }
#pragma unroll
        for (int j = 0; j < 4; j++) {
#pragma unroll
            for (int mi = 0; mi < 2; mi++) {
                mma_bf16(acc[mi][j], ah[mi].x, ah[mi].y, ah[mi].z, ah[mi].w,
                         bh[j].x, bh[j].y);
                mma_bf16(acc[mi][j], ah[mi].x, ah[mi].y, ah[mi].z, ah[mi].w,
                         bl[j].x, bl[j].y);
                mma_bf16(acc[mi][j], al[mi].x, al[mi].y, al[mi].z, al[mi].w,
                         bh[j].x, bh[j].y);
            }
        }
    }

#pragma unroll
    for (int j = 0; j < 4; j++) {
        int n = (n8_0 + j) * 8 + tig * 2;
        float bx = b_ih[n] + b_hh[n];
        float by = b_ih[n + 1] + b_hh[n + 1];
#pragma unroll
        for (int mi = 0; mi < 2; mi++) {
            int m0r = (mt0 + mi) * 16 + g;
            *(float2*)&C[(size_t)m0r * G4 + n] =
                make_float2(acc[mi][j][0] + bx, acc[mi][j][1] + by);
            *(float2*)&C[(size_t)(m0r + 8) * G4 + n] =
                make_float2(acc[mi][j][2] + bx, acc[mi][j][3] + by);
        }
    }
}

// ---------------------------------------------------------------------------
// 2) Persistent recurrence v2: 128 CTAs x 8 cells, full-K, smem-staged h,
//    ldmatrix B feeds, in-register LSTM state, grid barrier per step.
// ---------------------------------------------------------------------------
__global__ __launch_bounds__(NTT, 1)
void rnn_persistent2(const float* __restrict__ c0,
                     float* __restrict__ out) {
    extern __shared__ char smem[];
    const uint32_t sbase = smem_u32p(smem);

    const int tid  = threadIdx.x;
    const int lane = tid & 31;
    const int wn   = tid >> 5;          // warp owns batches wn*8..+7
    const int nt   = blockIdx.x;        // cells nt*8..+7
    const int g    = lane >> 2;
    const int tig  = lane & 3;

    // A fragment pointers (uint4): [nt][mi][ks][lane]
    const uint4* aH0 = (const uint4*)g_wpA2_hi + ((size_t)(nt * 2 + 0) * NKS) * 32 + lane;
    const uint4* aH1 = (const uint4*)g_wpA2_hi + ((size_t)(nt * 2 + 1) * NKS) * 32 + lane;
    const uint4* aL0 = (const uint4*)g_wpA2_lo + ((size_t)(nt * 2 + 0) * NKS) * 32 + lane;
    const uint4* aL1 = (const uint4*)g_wpA2_lo + ((size_t)(nt * 2 + 1) * NKS) * 32 + lane;

    // ldmatrix lane address offset within a chunk matrix
    const uint32_t lmOff = (uint32_t)((lane & 15) * BSROW + wn * 16);

    // epilogue identity: cell = nt*8+g, batches b0,b0+1
    const int cell = nt * 8 + g;
    const int b0   = wn * 8 + tig * 2;

    // c state in registers for the whole run
    float c_reg0 = c0[b0 * H_ + cell];
    float c_reg1 = c0[(b0 + 1) * H_ + cell];

    for (int t = 0; t < S_; t++) {
        // prefetch xg gate values for this step
        float xp[4][2];
#pragma unroll
        for (int gg = 0; gg < 4; gg++) {
            const float* xr = g_xg + (size_t)(t * B_ + b0) * G4 + gg * H_ + cell;
            xp[gg][0] = __ldg(xr);
            xp[gg][1] = __ldg(xr + G4);
        }

        float acc[2][4];
#pragma unroll
        for (int i = 0; i < 2; i++)
#pragma unroll
            for (int c = 0; c < 4; c++) acc[i][c] = 0.0f;

        // stage chunk 0
        {
#pragma unroll
            for (int i = 0; i < 8; i++) {
                int lin = i * NTT + tid;
                int mat = lin >> 10;
                int within = lin & 1023;
                int row = within >> 3;
                int col = within & 7;
                const uint4* gsrc = ((const uint4*)(mat ? g_hT_lo : g_hT_hi))
                                    + (size_t)row * 8 + col;
                cp16(sbase + (0 * 2 + mat) * CHUNK_BYTES + row * BSROW + col * 16,
                     gsrc);
            }
            asm volatile("cp.async.commit_group;" ::: "memory");
        }

        for (int c = 0; c < NCHUNK; c++) {
            const int buf = c & 1;
            if (c + 1 < NCHUNK) {
                const int nbuf = (c + 1) & 1;
#pragma unroll
                for (int i = 0; i < 8; i++) {
                    int lin = i * NTT + tid;
                    int mat = lin >> 10;
                    int within = lin & 1023;
                    int row = within >> 3;
                    int col = within & 7;
                    const uint4* gsrc = ((const uint4*)(mat ? g_hT_lo : g_hT_hi))
                        + (size_t)((c + 1) * CHUNK_ROWS + row) * 8 + col;
                    cp16(sbase + (nbuf * 2 + mat) * CHUNK_BYTES + row * BSROW + col * 16,
                         gsrc);
                }
                asm volatile("cp.async.commit_group;" ::: "memory");
                asm volatile("cp.async.wait_group 1;" ::: "memory");
            } else {
                asm volatile("cp.async.wait_group 0;" ::: "memory");
            }
            __syncthreads();

            const uint32_t bHbase = sbase + (buf * 2 + 0) * CHUNK_BYTES + lmOff;
            const uint32_t bLbase = sbase + (buf * 2 + 1) * CHUNK_BYTES + lmOff;

#pragma unroll
            for (int kl = 0; kl < CHUNK_ROWS / 16; kl++) {   // 8 k16-steps
                int ks = c * (CHUNK_ROWS / 16) + kl;
                uint4 a0h = __ldg(aH0 + (size_t)ks * 32);
                uint4 a1h = __ldg(aH1 + (size_t)ks * 32);
                uint4 a0l = __ldg(aL0 + (size_t)ks * 32);
                uint4 a1l = __ldg(aL1 + (size_t)ks * 32);

                uint32_t bh0, bh1, bl0, bl1;
                ldsm_x2_t(bh0, bh1, bHbase + kl * 16 * BSROW);
                ldsm_x2_t(bl0, bl1, bLbase + kl * 16 * BSROW);

                mma_bf16(acc[0], a0h.x, a0h.y, a0h.z, a0h.w, bh0, bh1);
                mma_bf16(acc[1], a1h.x, a1h.y, a1h.z, a1h.w, bh0, bh1);
                mma_bf16(acc[0], a0h.x, a0h.y, a0h.z, a0h.w, bl0, bl1);
                mma_bf16(acc[1], a1h.x, a1h.y, a1h.z, a1h.w, bl0, bl1);
                mma_bf16(acc[0], a0l.x, a0l.y, a0l.z, a0l.w, bh0, bh1);
                mma_bf16(acc[1], a1l.x, a1l.y, a1l.z, a1l.w, bh0, bh1);
            }
            __syncthreads();
        }

        // in-register LSTM update:
        // acc[0][0,1]=i(b0,b1)  acc[0][2,3]=f  acc[1][0,1]=g  acc[1][2,3]=o
        float i0 = acc[0][0] + xp[0][0], i1 = acc[0][1] + xp[0][1];
        float f0 = acc[0][2] + xp[1][0], f1 = acc[0][3] + xp[1][1];
        float gg0 = acc[1][0] + xp[2][0], gg1 = acc[1][1] + xp[2][1];
        float o0 = acc[1][2] + xp[3][0], o1 = acc[1][3] + xp[3][1];

        c_reg0 = sigf(f0) * c_reg0 + sigf(i0) * tanhfast(gg0);
        c_reg1 = sigf(f1) * c_reg1 + sigf(i1) * tanhfast(gg1);
        float h0v = sigf(o0) * tanhfast(c_reg0);
        float h1v = sigf(o1) * tanhfast(c_reg1);

        out[((size_t)b0 * S_ + t) * H_ + cell] = h0v;
        out[((size_t)(b0 + 1) * S_ + t) * H_ + cell] = h1v;

        float l0, l1;
        uint32_t hiw = pack_hi(h0v, h1v, l0, l1);
        uint32_t low = pack_bf2(l0, l1);
        *(uint32_t*)&g_hT_hi[cell * B_ + b0] = hiw;
        *(uint32_t*)&g_hT_lo[cell * B_ + b0] = low;

        // grid barrier (monotone counter; proven R6 scheme)
        __syncthreads();
        if (t < S_ - 1) {
            if (tid == 0) {
                __threadfence();
                atomicAdd(&g_bar, 1u);
                unsigned target = (unsigned)NCTA * (t + 1);
                unsigned v;
                do {
                    asm volatile("ld.global.acquire.gpu.u32 %0, [%1];"
                                 : "=r"(v) : "l"(&g_bar));
                } while (v < target);
            }
            __syncthreads();
        } else {
            if (tid == 0) {
                __threadfence();
                unsigned old = atomicAdd(&g_bar, 1u);
                if (old == (unsigned)NCTA * S_ - 1u)
                    atomicExch(&g_bar, 0u);   // reset for graph replay
            }
        }
    }
}

// ---------------------------------------------------------------------------
// Launcher
// ---------------------------------------------------------------------------
extern "C" void kernel_launch(void* const* d_in, const int* in_sizes, int n_in,
                              void* d_out, int out_size) {
    const float* features = (const float*)d_in[0];
    const int*   captions = (const int*)  d_in[1];
    const float* W_embed  = (const float*)d_in[2];
    const float* b_embed  = (const float*)d_in[3];
    const float* w_ih     = (const float*)d_in[4];
    const float* w_hh     = (const float*)d_in[5];
    const float* b_ih     = (const float*)d_in[6];
    const float* b_hh     = (const float*)d_in[7];
    const float* h0       = (const float*)d_in[8];
    const float* c0       = (const float*)d_in[9];
    float* out = (float*)d_out;

    cudaFuncSetAttribute(rnn_persistent2,
                         cudaFuncAttributeMaxDynamicSharedMemorySize, SMEM_SZ);

    float* pxg;
    cudaGetSymbolAddress((void**)&pxg, g_xg);

    // prep: packs + state init
    prep_wpack2<<<(PACK2_U32 + 255) / 256, 256>>>(w_hh);
    prep_wih<<<(WIH_U32 + 255) / 256, 256>>>(w_ih);
    build_x_pack<<<(XA_U32 + 255) / 256, 256>>>(features, captions, W_embed, b_embed);
    init_h_kernel<<<(B_ * H_ + 255) / 256, 256>>>(h0);

    // input projection (bias folded in)
    gemm_xg_bf16<<<dim3(M1 / 64, G4 / 128), NTT>>>(b_ih, b_hh, pxg);

    // persistent recurrence
    rnn_persistent2<<<NCTA, NTT, SMEM_SZ>>>(c0, out);
}

// round 8
// speedup vs baseline: 2.2011x; 1.1834x over previous
#include <cuda_runtime.h>
#include <cuda_bf16.h>
#include <math.h>
#include <stdint.h>

// Problem constants
#define B_  64
#define T_  32
#define S_  33
#define V_  32000
#define E_  512
#define H_  1024
#define G4  4096
#define M1  (S_*B_)       // 2112

// recurrence config: 128 CTAs x 8 cells, warps split over K
#define NCTA  128
#define NTT   256         // 8 warps
#define NKS   64          // k16 steps
#define CHUNK_ROWS 128
#define NCHUNK (H_/CHUNK_ROWS)   // 8
#define BSROW  144
#define CHUNK_BYTES (CHUNK_ROWS*BSROW)   // 18432
#define HBUF_BYTES (2*2*CHUNK_BYTES)     // 73728 (buf x {hi,lo})
#define RQS    66                         // red q-stride (floats)
#define SMEM_C_OFF HBUF_BYTES             // c state after h bufs
#define SMEM_TOTAL (HBUF_BYTES + 2048)    // 75776

// packs
#define PACK2_U32 (NCTA*2*NKS*32*4)
#define XTILES    (M1/16)
#define XA_U32    (XTILES*32*32*4)
#define WIH_U32   (512*32*32*2)

// ---------------- device scratch ----------------
__device__ float g_xg2[M1 * G4];             // [t][gate*1024+cell][batch]
__device__ uint32_t g_wpA2_hi[PACK2_U32];
__device__ uint32_t g_wpA2_lo[PACK2_U32];
__device__ uint32_t g_xA_hi[XA_U32];
__device__ uint32_t g_xA_lo[XA_U32];
__device__ uint32_t g_wihB_hi[WIH_U32];
__device__ uint32_t g_wihB_lo[WIH_U32];
__device__ __nv_bfloat16 g_hT_hi[H_ * B_];   // [cell][batch]
__device__ __nv_bfloat16 g_hT_lo[H_ * B_];
__device__ unsigned g_bar;

__device__ __forceinline__ float sigf(float x) {
    return 1.0f / (1.0f + __expf(-x));
}
__device__ __forceinline__ float tanhfast(float x) {
    return 2.0f / (1.0f + __expf(-2.0f * x)) - 1.0f;
}
__device__ __forceinline__ void mma_bf16(float* d, uint32_t a0, uint32_t a1,
                                         uint32_t a2, uint32_t a3,
                                         uint32_t b0, uint32_t b1) {
    asm volatile(
        "mma.sync.aligned.m16n8k16.row.col.f32.bf16.bf16.f32 "
        "{%0,%1,%2,%3}, {%4,%5,%6,%7}, {%8,%9}, {%0,%1,%2,%3};"
        : "+f"(d[0]), "+f"(d[1]), "+f"(d[2]), "+f"(d[3])
        : "r"(a0), "r"(a1), "r"(a2), "r"(a3), "r"(b0), "r"(b1));
}
__device__ __forceinline__ uint32_t pack_hi(float v0, float v1,
                                            float& l0, float& l1) {
    __nv_bfloat16 h0 = __float2bfloat16(v0);
    __nv_bfloat16 h1 = __float2bfloat16(v1);
    l0 = v0 - __bfloat162float(h0);
    l1 = v1 - __bfloat162float(h1);
    return (uint32_t)__bfloat16_as_ushort(h0)
         | ((uint32_t)__bfloat16_as_ushort(h1) << 16);
}
__device__ __forceinline__ uint32_t pack_bf2(float v0, float v1) {
    return (uint32_t)__bfloat16_as_ushort(__float2bfloat16(v0))
         | ((uint32_t)__bfloat16_as_ushort(__float2bfloat16(v1)) << 16);
}
__device__ __forceinline__ uint32_t smem_u32p(const void* p) {
    uint32_t a;
    asm("{ .reg .u64 t; cvta.to.shared.u64 t, %1; cvt.u32.u64 %0, t; }"
        : "=r"(a) : "l"(p));
    return a;
}
__device__ __forceinline__ void cp16(uint32_t sdst, const void* gsrc) {
    asm volatile("cp.async.cg.shared.global [%0], [%1], 16;"
                 :: "r"(sdst), "l"(gsrc) : "memory");
}
__device__ __forceinline__ void ldsm_x2_t(uint32_t& r0, uint32_t& r1,
                                          uint32_t addr) {
    asm volatile("ldmatrix.sync.aligned.m8n8.x2.trans.shared.b16 {%0,%1}, [%2];"
                 : "=r"(r0), "=r"(r1) : "r"(addr));
}

// ---------------------------------------------------------------------------
// 0a) Pack w_hh into A-frag order (rows q = gate*8+cell), proven
// ---------------------------------------------------------------------------
__global__ void prep_wpack2(const float* __restrict__ w_hh) {
    int idx = blockIdx.x * 256 + threadIdx.x;
    if (idx >= PACK2_U32) return;
    int r    = idx & 3;
    int lane = (idx >> 2) & 31;
    int ks   = (idx >> 7) & 63;
    int mi   = (idx >> 13) & 1;
    int nt   = idx >> 14;
    int row16 = (lane >> 2) + ((r & 1) << 3);
    int colp  = (lane & 3) * 2 + ((r >> 1) << 3);
    int q = mi * 16 + row16;
    int gate = q >> 3, cl = q & 7;
    const float* src = w_hh + (size_t)(gate * H_ + nt * 8 + cl) * H_ + ks * 16 + colp;
    float v0 = src[0], v1 = src[1], l0, l1;
    g_wpA2_hi[idx] = pack_hi(v0, v1, l0, l1);
    g_wpA2_lo[idx] = pack_bf2(l0, l1);
}

// 0b) Pack w_ih into B-frag order (proven)
__global__ void prep_wih(const float* __restrict__ w_ih) {
    int idx = blockIdx.x * 256 + threadIdx.x;
    if (idx >= WIH_U32) return;
    int r    = idx & 1;
    int lane = (idx >> 1) & 31;
    int ks   = (idx >> 6) & 31;
    int n8   = idx >> 11;
    int n = n8 * 8 + (lane >> 2);
    int k = ks * 16 + (lane & 3) * 2 + r * 8;
    const float* src = w_ih + (size_t)n * E_ + k;
    float v0 = src[0], v1 = src[1], l0, l1;
    g_wihB_hi[idx] = pack_hi(v0, v1, l0, l1);
    g_wihB_lo[idx] = pack_bf2(l0, l1);
}

// 0c) Build x in A-frag order (proven)
__global__ void build_x_pack(const float* __restrict__ features,
                             const int*   __restrict__ captions,
                             const float* __restrict__ W_embed,
                             const float* __restrict__ b_embed) {
    int idx = blockIdx.x * 256 + threadIdx.x;
    if (idx >= XA_U32) return;
    int rr   = idx & 3;
    int lane = (idx >> 2) & 31;
    int ks   = (idx >> 7) & 31;
    int mt   = idx >> 12;
    int row16 = (lane >> 2) + ((rr & 1) << 3);
    int colp  = (lane & 3) * 2 + ((rr >> 1) << 3);
    int m = mt * 16 + row16;
    int k = ks * 16 + colp;
    int t = m >> 6, b = m & 63;
    float v0, v1;
    if (t == 0) {
        v0 = features[b * E_ + k];
        v1 = features[b * E_ + k + 1];
    } else {
        int cap = captions[b * T_ + (t - 1)];
        v0 = W_embed[(size_t)k * V_ + cap] + b_embed[k];
        v1 = W_embed[(size_t)(k + 1) * V_ + cap] + b_embed[k + 1];
    }
    float l0, l1;
    g_xA_hi[idx] = pack_hi(v0, v1, l0, l1);
    g_xA_lo[idx] = pack_bf2(l0, l1);
}

// 0d) Init h transposed [cell][batch]
__global__ void init_h_kernel(const float* __restrict__ h0) {
    int idx = blockIdx.x * 256 + threadIdx.x;
    if (idx >= B_ * H_) return;
    int cell = idx >> 6;
    int b    = idx & 63;
    float v = h0[b * H_ + cell];
    __nv_bfloat16 hi = __float2bfloat16(v);
    g_hT_hi[idx] = hi;
    g_hT_lo[idx] = __float2bfloat16(v - __bfloat162float(hi));
}

// ---------------------------------------------------------------------------
// 1) xg2[t][n][b] = x @ w_ih^T + bias (bf16 hi/lo HMMA; epilogue re-laid-out)
// ---------------------------------------------------------------------------
__global__ __launch_bounds__(NTT, 1)
void gemm_xg_bf16(const float* __restrict__ b_ih,
                  const float* __restrict__ b_hh,
                  float* __restrict__ C) {
    const int tid  = threadIdx.x;
    const int wid  = tid >> 5;
    const int lane = tid & 31;
    const int wm   = wid & 1;
    const int wn   = wid >> 1;
    const int tt   = blockIdx.x;              // one t per block (64 rows)
    const int mt0  = tt * 4 + wm * 2;
    const int n8_0 = blockIdx.y * 16 + wn * 4;
    const int g    = lane >> 2;
    const int tig  = lane & 3;

    const uint4* aH = (const uint4*)g_xA_hi;
    const uint4* aL = (const uint4*)g_xA_lo;
    const uint2* bH = (const uint2*)g_wihB_hi;
    const uint2* bL = (const uint2*)g_wihB_lo;

    float acc[2][4][4];
#pragma unroll
    for (int i = 0; i < 2; i++)
#pragma unroll
        for (int j = 0; j < 4; j++)
#pragma unroll
            for (int c = 0; c < 4; c++) acc[i][j][c] = 0.0f;

#pragma unroll 4
    for (int ks = 0; ks < 32; ks++) {
        uint4 ah[2], al[2];
#pragma unroll
        for (int mi = 0; mi < 2; mi++) {
            size_t ai = ((size_t)(mt0 + mi) * 32 + ks) * 32 + lane;
            ah[mi] = __ldg(&aH[ai]);
            al[mi] = __ldg(&aL[ai]);
        }
        uint2 bh[4], bl[4];
#pragma unroll
        for (int j = 0; j < 4; j++) {
            size_t bix = ((size_t)(n8_0 + j) * 32 + ks) * 32 + lane;
            bh[j] = __ldg(&bH[bix]);
            bl[j] = __ldg(&bL[bix]);
        }
#pragma unroll
        for (int j = 0; j < 4; j++) {
#pragma unroll
            for (int mi = 0; mi < 2; mi++) {
                mma_bf16(acc[mi][j], ah[mi].x, ah[mi].y, ah[mi].z, ah[mi].w,
                         bh[j].x, bh[j].y);
                mma_bf16(acc[mi][j], ah[mi].x, ah[mi].y, ah[mi].z, ah[mi].w,
                         bl[j].x, bl[j].y);
                mma_bf16(acc[mi][j], al[mi].x, al[mi].y, al[mi].z, al[mi].w,
                         bh[j].x, bh[j].y);
            }
        }
    }

    // epilogue: C[(t*4096 + n)*64 + b] = acc + bias
#pragma unroll
    for (int j = 0; j < 4; j++) {
        int n = (n8_0 + j) * 8 + tig * 2;
        float bx = b_ih[n] + b_hh[n];
        float by = b_ih[n + 1] + b_hh[n + 1];
        float* c0p = C + ((size_t)tt * G4 + n) * 64;
        float* c1p = C + ((size_t)tt * G4 + n + 1) * 64;
#pragma unroll
        for (int mi = 0; mi < 2; mi++) {
            int b = (wm * 2 + mi) * 16 + g;
            c0p[b]     = acc[mi][j][0] + bx;
            c1p[b]     = acc[mi][j][1] + by;
            c0p[b + 8] = acc[mi][j][2] + bx;
            c1p[b + 8] = acc[mi][j][3] + by;
        }
    }
}

// ---------------------------------------------------------------------------
// 2) Persistent recurrence v3: warps split over K (A frags read once/CTA),
//    full n=64 per warp, cross-warp reduce in smem (overlays h buffers),
//    c state in smem, grid barrier per step.
// ---------------------------------------------------------------------------
__global__ __launch_bounds__(NTT, 1)
void rnn_persistent3(const float* __restrict__ c0,
                     float* __restrict__ out) {
    extern __shared__ char smem[];
    const uint32_t sbase = smem_u32p(smem);
    float* red  = (float*)smem;                      // overlays h buffers
    float* c_sm = (float*)(smem + SMEM_C_OFF);       // [cell8][batch64]

    const int tid  = threadIdx.x;
    const int lane = tid & 31;
    const int w    = tid >> 5;          // warp owns ks = 8c + w
    const int nt   = blockIdx.x;        // cells nt*8..+7
    const int g    = lane >> 2;
    const int tig  = lane & 3;

    // A fragment pointers: [nt][mi][ks][lane] uint4
    const uint4* aH0 = (const uint4*)g_wpA2_hi + ((size_t)(nt * 2 + 0) * NKS) * 32 + lane;
    const uint4* aH1 = (const uint4*)g_wpA2_hi + ((size_t)(nt * 2 + 1) * NKS) * 32 + lane;
    const uint4* aL0 = (const uint4*)g_wpA2_lo + ((size_t)(nt * 2 + 0) * NKS) * 32 + lane;
    const uint4* aL1 = (const uint4*)g_wpA2_lo + ((size_t)(nt * 2 + 1) * NKS) * 32 + lane;

    // ldmatrix base within a chunk: warp's k-rows at offset w*16, lane rows
    const uint32_t lmRow = (uint32_t)((w * 16 + (lane & 15)) * BSROW);

    // epilogue mapping: thread -> (cl, batches b0e, b0e+1)
    const int cl  = tid >> 5;
    const int b0e = (tid & 31) * 2;
    const int cell = nt * 8 + cl;

    // init c state in smem
    c_sm[cl * 64 + b0e]     = c0[b0e * H_ + cell];
    c_sm[cl * 64 + b0e + 1] = c0[(b0e + 1) * H_ + cell];
    __syncthreads();

    for (int t = 0; t < S_; t++) {
        float acc[2][8][4];
#pragma unroll
        for (int i = 0; i < 2; i++)
#pragma unroll
            for (int j = 0; j < 8; j++)
#pragma unroll
                for (int c = 0; c < 4; c++) acc[i][j][c] = 0.0f;

        // stage chunk 0
#pragma unroll
        for (int i = 0; i < 8; i++) {
            int lin = i * NTT + tid;
            int mat = lin >> 10;
            int within = lin & 1023;
            int row = within >> 3;
            int col = within & 7;
            const uint4* gsrc = ((const uint4*)(mat ? g_hT_lo : g_hT_hi))
                                + (size_t)row * 8 + col;
            cp16(sbase + mat * CHUNK_BYTES + row * BSROW + col * 16, gsrc);
        }
        asm volatile("cp.async.commit_group;" ::: "memory");

        for (int c = 0; c < NCHUNK; c++) {
            const int buf = c & 1;
            if (c + 1 < NCHUNK) {
                const int nbuf = (c + 1) & 1;
#pragma unroll
                for (int i = 0; i < 8; i++) {
                    int lin = i * NTT + tid;
                    int mat = lin >> 10;
                    int within = lin & 1023;
                    int row = within >> 3;
                    int col = within & 7;
                    const uint4* gsrc = ((const uint4*)(mat ? g_hT_lo : g_hT_hi))
                        + (size_t)((c + 1) * CHUNK_ROWS + row) * 8 + col;
                    cp16(sbase + (nbuf * 2 + mat) * CHUNK_BYTES + row * BSROW + col * 16,
                         gsrc);
                }
                asm volatile("cp.async.commit_group;" ::: "memory");
                asm volatile("cp.async.wait_group 1;" ::: "memory");
            } else {
                asm volatile("cp.async.wait_group 0;" ::: "memory");
            }
            __syncthreads();

            // warp w computes its k16-slice ks = c*8 + w over all 8 n8 tiles
            const int ks = c * 8 + w;
            uint4 a0h = __ldg(aH0 + (size_t)ks * 32);
            uint4 a1h = __ldg(aH1 + (size_t)ks * 32);
            uint4 a0l = __ldg(aL0 + (size_t)ks * 32);
            uint4 a1l = __ldg(aL1 + (size_t)ks * 32);

            const uint32_t bHbase = sbase + (buf * 2 + 0) * CHUNK_BYTES + lmRow;
            const uint32_t bLbase = sbase + (buf * 2 + 1) * CHUNK_BYTES + lmRow;

            uint32_t bh[8][2], bl[8][2];
#pragma unroll
            for (int j = 0; j < 8; j++) {
                ldsm_x2_t(bh[j][0], bh[j][1], bHbase + j * 16);
                ldsm_x2_t(bl[j][0], bl[j][1], bLbase + j * 16);
            }
#pragma unroll
            for (int j = 0; j < 8; j++) {
                mma_bf16(acc[0][j], a0h.x, a0h.y, a0h.z, a0h.w, bh[j][0], bh[j][1]);
                mma_bf16(acc[1][j], a1h.x, a1h.y, a1h.z, a1h.w, bh[j][0], bh[j][1]);
                mma_bf16(acc[0][j], a0h.x, a0h.y, a0h.z, a0h.w, bl[j][0], bl[j][1]);
                mma_bf16(acc[1][j], a1h.x, a1h.y, a1h.z, a1h.w, bl[j][0], bl[j][1]);
                mma_bf16(acc[0][j], a0l.x, a0l.y, a0l.z, a0l.w, bh[j][0], bh[j][1]);
                mma_bf16(acc[1][j], a1l.x, a1l.y, a1l.z, a1l.w, bh[j][0], bh[j][1]);
            }
            __syncthreads();
        }

        // cross-warp reduce: warp partials -> red[w][q][b] (overlays h bufs)
#pragma unroll
        for (int mi = 0; mi < 2; mi++) {
            int q = mi * 16 + g;
#pragma unroll
            for (int j = 0; j < 8; j++) {
                int col = j * 8 + tig * 2;
                *(float2*)&red[(size_t)(w * 32 + q) * RQS + col] =
                    make_float2(acc[mi][j][0], acc[mi][j][1]);
                *(float2*)&red[(size_t)(w * 32 + q + 8) * RQS + col] =
                    make_float2(acc[mi][j][2], acc[mi][j][3]);
            }
        }
        __syncthreads();

        // fused LSTM epilogue: thread (cl, b0e, b0e+1)
        {
            float2 gv[4];
#pragma unroll
            for (int gate = 0; gate < 4; gate++) {
                int q = gate * 8 + cl;
                float2 s = *(const float2*)
                    &g_xg2[((size_t)t * G4 + gate * H_ + cell) * 64 + b0e];
#pragma unroll
                for (int ww = 0; ww < 8; ww++) {
                    float2 p = *(const float2*)&red[(size_t)(ww * 32 + q) * RQS + b0e];
                    s.x += p.x; s.y += p.y;
                }
                gv[gate] = s;
            }
            float cA = c_sm[cl * 64 + b0e];
            float cB = c_sm[cl * 64 + b0e + 1];
            cA = sigf(gv[1].x) * cA + sigf(gv[0].x) * tanhfast(gv[2].x);
            cB = sigf(gv[1].y) * cB + sigf(gv[0].y) * tanhfast(gv[2].y);
            float hA = sigf(gv[3].x) * tanhfast(cA);
            float hB = sigf(gv[3].y) * tanhfast(cB);
            c_sm[cl * 64 + b0e]     = cA;
            c_sm[cl * 64 + b0e + 1] = cB;

            out[((size_t)b0e * S_ + t) * H_ + cell] = hA;
            out[((size_t)(b0e + 1) * S_ + t) * H_ + cell] = hB;

            float l0, l1;
            uint32_t hiw = pack_hi(hA, hB, l0, l1);
            uint32_t low = pack_bf2(l0, l1);
            *(uint32_t*)&g_hT_hi[cell * B_ + b0e] = hiw;
            *(uint32_t*)&g_hT_lo[cell * B_ + b0e] = low;
        }

        // grid barrier (proven monotone scheme)
        __syncthreads();
        if (t < S_ - 1) {
            if (tid == 0) {
                __threadfence();
                atomicAdd(&g_bar, 1u);
                unsigned target = (unsigned)NCTA * (t + 1);
                unsigned v;
                do {
                    asm volatile("ld.global.acquire.gpu.u32 %0, [%1];"
                                 : "=r"(v) : "l"(&g_bar));
                } while (v < target);
            }
            __syncthreads();
        } else {
            if (tid == 0) {
                __threadfence();
                unsigned old = atomicAdd(&g_bar, 1u);
                if (old == (unsigned)NCTA * S_ - 1u)
                    atomicExch(&g_bar, 0u);   // reset for graph replay
            }
        }
    }
}

// ---------------------------------------------------------------------------
// Launcher
// ---------------------------------------------------------------------------
extern "C" void kernel_launch(void* const* d_in, const int* in_sizes, int n_in,
                              void* d_out, int out_size) {
    const float* features = (const float*)d_in[0];
    const int*   captions = (const int*)  d_in[1];
    const float* W_embed  = (const float*)d_in[2];
    const float* b_embed  = (const float*)d_in[3];
    const float* w_ih     = (const float*)d_in[4];
    const float* w_hh     = (const float*)d_in[5];
    const float* b_ih     = (const float*)d_in[6];
    const float* b_hh     = (const float*)d_in[7];
    const float* h0       = (const float*)d_in[8];
    const float* c0       = (const float*)d_in[9];
    float* out = (float*)d_out;

    cudaFuncSetAttribute(rnn_persistent3,
                         cudaFuncAttributeMaxDynamicSharedMemorySize, SMEM_TOTAL);

    float* pxg;
    cudaGetSymbolAddress((void**)&pxg, g_xg2);

    // prep: packs + state init
    prep_wpack2<<<(PACK2_U32 + 255) / 256, 256>>>(w_hh);
    prep_wih<<<(WIH_U32 + 255) / 256, 256>>>(w_ih);
    build_x_pack<<<(XA_U32 + 255) / 256, 256>>>(features, captions, W_embed, b_embed);
    init_h_kernel<<<(B_ * H_ + 255) / 256, 256>>>(h0);

    // input projection (bias folded, [t][n][b] layout)
    gemm_xg_bf16<<<dim3(M1 / 64, G4 / 128), NTT>>>(b_ih, b_hh, pxg);

    // persistent recurrence
    rnn_persistent3<<<NCTA, NTT, SMEM_TOTAL>>>(c0, out);
}